// round 13
// baseline (speedup 1.0000x reference)
#include <cuda_runtime.h>
#include <cuda_fp16.h>
#include <math.h>

#define NN 200000
#define NE 1600000
#define NB 1000
#define H  128
#define NBLK 196          // ceil(NN/1024)

// ------------------------- device scratch (no allocs allowed) ----------------
__device__ float    g_xw [(size_t)NN * H]; // dinv*xW_gcn (fp32), reused nowhere else
__device__ unsigned g_h0h[(size_t)NN * 64]; // h0 as packed half2 pairs (128 f)
__device__ float    g_deg[NN];             // dinv
__device__ double   g_stats[6 * H];        // sum0,sq0,sum1,sq1,sum2,sq2
__device__ float    g_W1f[H * H];          // BN0-folded W1
__device__ float    g_b1f[H];
__device__ float    g_W3a[H], g_W3b[H];    // c1 = s1*w3a, c2 = s2*w3b
__device__ float    g_c;
__device__ float    g_S[2 * NB * H];       // per-graph raw sums of h1 | h2
__device__ float    g_gcnt[NB];
__device__ int      g_is64;
// CSR-ish edge structures (counting sort by dst)
__device__ int      g_cnt[NN];
__device__ int      g_off[NN];
__device__ int      g_cur[NN];
__device__ int      g_ssrc[NE];
__device__ int      g_bsum[256];
// Pre-split, pre-swizzled fp16 hi/lo weight images (SMEM-verbatim layout)
__device__ __align__(16) unsigned char g_Bh[65536];
__device__ __align__(16) unsigned char g_Bl[65536];

// ------------------------- small helpers -------------------------------------
__device__ __forceinline__ unsigned smem_u32(const void* p) {
    unsigned a;
    asm("{ .reg .u64 t; cvta.to.shared.u64 t, %1; cvt.u32.u64 %0, t; }"
        : "=r"(a) : "l"(p));
    return a;
}
__device__ __forceinline__ unsigned h2pack(float a, float b) {
    __half2 h = __floats2half2_rn(a, b);
    return *(unsigned*)&h;
}

#define LDSM4(r0, r1, r2, r3, a) \
    asm volatile("ldmatrix.sync.aligned.m8n8.x4.shared.b16 {%0,%1,%2,%3}, [%4];" \
                 : "=r"(r0), "=r"(r1), "=r"(r2), "=r"(r3) : "r"(a))
#define LDSM4T(r0, r1, r2, r3, a) \
    asm volatile("ldmatrix.sync.aligned.m8n8.x4.trans.shared.b16 {%0,%1,%2,%3}, [%4];" \
                 : "=r"(r0), "=r"(r1), "=r"(r2), "=r"(r3) : "r"(a))

__device__ __forceinline__ void hmma(float* c, const unsigned* a, const unsigned* b) {
    asm volatile(
        "mma.sync.aligned.m16n8k16.row.col.f32.f16.f16.f32 "
        "{%0,%1,%2,%3}, {%4,%5,%6,%7}, {%8,%9}, {%0,%1,%2,%3};"
        : "+f"(c[0]), "+f"(c[1]), "+f"(c[2]), "+f"(c[3])
        : "r"(a[0]), "r"(a[1]), "r"(a[2]), "r"(a[3]), "r"(b[0]), "r"(b[1]));
}

// ------------------------- misc small kernels --------------------------------
__global__ void k_detect(const long long* __restrict__ ei) {
    if (threadIdx.x == 0) {
        int ok = 1;
        for (int i = 0; i < 128; i++) {
            long long v = ei[i];
            if (v < 0 || v >= NN) ok = 0;
        }
        g_is64 = ok;
    }
}
__global__ void k_init() {
    int i = blockIdx.x * blockDim.x + threadIdx.x;
    if (i < NN) g_cnt[i] = 0;
    if (i < 2 * NB * H) g_S[i] = 0.f;
    if (i < 6 * H) g_stats[i] = 0.0;
    if (i < NB) g_gcnt[i] = 0.f;
}
__global__ void k_bhist(const long long* __restrict__ b64,
                        const int* __restrict__ b32) {
    int is64 = g_is64;
    int n = blockIdx.x * blockDim.x + threadIdx.x;
    if (n < NN) {
        int g = is64 ? (int)b64[n] : b32[n];
        atomicAdd(&g_gcnt[g], 1.f);
    }
}
__global__ void k_hist(const long long* __restrict__ e64,
                       const int* __restrict__ e32) {
    int is64 = g_is64;
    for (int e = blockIdx.x * blockDim.x + threadIdx.x; e < NE;
         e += gridDim.x * blockDim.x) {
        int d = is64 ? (int)e64[NE + e] : e32[NE + e];
        atomicAdd(&g_cnt[d], 1);
    }
}
__global__ void k_scan1() {
    __shared__ int sh[256];
    int blk = blockIdx.x, tid = threadIdx.x;
    int s = 0;
#pragma unroll
    for (int k = 0; k < 4; k++) {
        int i = blk * 1024 + tid + k * 256;
        if (i < NN) s += g_cnt[i];
    }
    sh[tid] = s; __syncthreads();
    for (int o = 128; o > 0; o >>= 1) {
        if (tid < o) sh[tid] += sh[tid + o];
        __syncthreads();
    }
    if (tid == 0) g_bsum[blk] = sh[0];
}
__global__ void k_scan2() {
    __shared__ int sh[256];
    int t = threadIdx.x;
    int v = (t < NBLK) ? g_bsum[t] : 0;
    sh[t] = v; __syncthreads();
    for (int o = 1; o < 256; o <<= 1) {
        int a = (t >= o) ? sh[t - o] : 0;
        __syncthreads();
        sh[t] += a;
        __syncthreads();
    }
    if (t < NBLK) g_bsum[t] = sh[t] - v;
}
__global__ void k_scan3() {
    __shared__ int tsum[256];
    int blk = blockIdx.x, tid = threadIdx.x;
    int i0 = blk * 1024 + tid * 4;
    int v[4];
#pragma unroll
    for (int j = 0; j < 4; j++) v[j] = (i0 + j < NN) ? g_cnt[i0 + j] : 0;
    int s = v[0] + v[1] + v[2] + v[3];
    tsum[tid] = s; __syncthreads();
    for (int o = 1; o < 256; o <<= 1) {
        int a = (tid >= o) ? tsum[tid - o] : 0;
        __syncthreads();
        tsum[tid] += a;
        __syncthreads();
    }
    int off = g_bsum[blk] + tsum[tid] - s;
#pragma unroll
    for (int j = 0; j < 4; j++) {
        int i = i0 + j;
        if (i < NN) {
            g_off[i] = off;
            g_cur[i] = off;
            g_deg[i] = rsqrtf((float)v[j] + 1.0f);
            off += v[j];
        }
    }
}
__global__ void k_sortedges(const long long* __restrict__ e64,
                            const int* __restrict__ e32) {
    int is64 = g_is64;
    for (int e = blockIdx.x * blockDim.x + threadIdx.x; e < NE;
         e += gridDim.x * blockDim.x) {
        int s, d;
        if (is64) { s = (int)e64[e]; d = (int)e64[NE + e]; }
        else      { s = e32[e];      d = e32[NE + e]; }
        int pos = atomicAdd(&g_cur[d], 1);
        g_ssrc[pos] = s;
    }
}

// ------------------------- weight prep: fp16 split + pre-swizzle -------------
template<int WHICH>
__global__ void k_prep(const float* __restrict__ srcp) {
    const int K   = (WHICH == 0) ? 64 : (WHICH == 1) ? 128 : 32;
    const int off = (WHICH == 0) ? 0 : (WHICH == 1) ? 16384 : 49152;
    const float* src = (WHICH == 1) ? (const float*)g_W1f : srcp;
    int idx = blockIdx.x * blockDim.x + threadIdx.x;
    if (idx >= K * 128) return;
    int k = idx >> 7, n = idx & 127;
    float v = src[k * 128 + n];
    __half h = __float2half_rn(v);
    __half l = __float2half_rn(v - __half2float(h));
    unsigned o = (unsigned)(k * 256 + (((n >> 3) ^ (k & 7)) * 16) + (n & 7) * 2);
    *(unsigned short*)(g_Bh + off + o) = __half_as_ushort(h);
    *(unsigned short*)(g_Bl + off + o) = __half_as_ushort(l);
}

// ------- fp16 mma.sync GEMM (2-pass: A*Bh + A*Bl): C[128,128]=A[128,K]@W ----
// EPI 0: g_xw = C * dinv (pre-scaled xw').                (A=x fp32, K=64)
// EPI 1: A = g_h0h (fp16 image); BN1 stats + per-graph sums S1.  (K=128)
// EPI 2: relu(C + cbias); BN2 stats + per-graph sums S2.  (A=action, K=32)
template<int K, int EPI>
__global__ void __launch_bounds__(256, 2)
k_bmma(const float* __restrict__ Aext, const float* __restrict__ cbias,
       const long long* __restrict__ bt64, const int* __restrict__ bt32) {
    constexpr int BK    = (K < 64) ? K : 64;
    constexpr int NST   = K / BK;
    constexpr int CPR   = BK / 8;
    constexpr int AMASK = (CPR < 8 ? CPR : 8) - 1;
    constexpr int ASZ   = 128 * BK * 2;
    constexpr int BSZ   = BK * 128 * 2;
    extern __shared__ __align__(128) unsigned char smem[];
    unsigned char* A_im = smem;
    unsigned char* B_hi = smem + ASZ;
    unsigned char* B_lo = smem + ASZ + BSZ;
    float* s_sum = (float*)(smem + ASZ + 2 * BSZ);
    float* s_sq  = s_sum + H;
    float (*S_loc)[H] = (float(*)[H])(s_sq + H);    // 8 x 128

    const int tid   = threadIdx.x;
    const int lane  = tid & 31;
    const int wid   = tid >> 5;
    const int mwarp = wid & 3;
    const int nwarp = wid >> 2;
    const int bm    = blockIdx.x * 128;
    const float* A  = Aext;
    const int boff  = (EPI == 0) ? 0 : (EPI == 1) ? 16384 : 49152;
    const int is64b = g_is64;

    if (EPI != 0) {
        if (tid < H) { s_sum[tid] = 0.f; s_sq[tid] = 0.f; }
#pragma unroll
        for (int i = tid; i < 8 * H; i += 256) S_loc[i >> 7][i & 127] = 0.f;
    }

    const unsigned uA  = smem_u32(A_im);
    const unsigned uBh = smem_u32(B_hi);
    const unsigned uBl = smem_u32(B_lo);

    float acc[2][8][4];
#pragma unroll
    for (int i = 0; i < 2; i++)
#pragma unroll
        for (int j = 0; j < 8; j++)
#pragma unroll
            for (int q = 0; q < 4; q++) acc[i][j][q] = 0.f;

    for (int st = 0; st < NST; st++) {
        if (st > 0) __syncthreads();

        {   // copy pre-swizzled B stage (L2-hot)
            const uint4* sh = (const uint4*)(g_Bh + boff + st * BK * 256);
            const uint4* sl = (const uint4*)(g_Bl + boff + st * BK * 256);
            uint4* dh = (uint4*)B_hi;
            uint4* dl = (uint4*)B_lo;
#pragma unroll
            for (int i = tid; i < BSZ / 16; i += 256) {
                dh[i] = sh[i]; dl[i] = sl[i];
            }
        }
        {   // build A fp16 image for this k-stage
            const int row0 = tid / CPR;
            const int c    = tid % CPR;
#pragma unroll
            for (int pass = 0; pass < CPR / 2; pass++) {
                int m  = row0 + pass * (256 / CPR);
                int gr = bm + m;
                uint4 hp;
                if (EPI == 1) {
                    hp = (gr < NN)
                        ? *(const uint4*)&g_h0h[(size_t)gr * 64 + (st * 8 + c) * 4]
                        : make_uint4(0, 0, 0, 0);
                } else {
                    const int kc = st * BK + c * 8;
                    float v[8];
                    if (gr < NN) {
                        float4 x0 = *(const float4*)&A[(size_t)gr * K + kc];
                        float4 x1 = *(const float4*)&A[(size_t)gr * K + kc + 4];
                        v[0] = x0.x; v[1] = x0.y; v[2] = x0.z; v[3] = x0.w;
                        v[4] = x1.x; v[5] = x1.y; v[6] = x1.z; v[7] = x1.w;
                    } else {
#pragma unroll
                        for (int j = 0; j < 8; j++) v[j] = 0.f;
                    }
                    hp.x = h2pack(v[0], v[1]);
                    hp.y = h2pack(v[2], v[3]);
                    hp.z = h2pack(v[4], v[5]);
                    hp.w = h2pack(v[6], v[7]);
                }
                unsigned o = (unsigned)(m * (BK * 2) + ((c ^ (m & AMASK)) * 16));
                *(uint4*)(A_im + o) = hp;
            }
        }
        __syncthreads();

#pragma unroll
        for (int k16 = 0; k16 < BK / 16; k16++) {
            unsigned ah[2][4];
#pragma unroll
            for (int mf = 0; mf < 2; mf++) {
                int row = mwarp * 32 + mf * 16 + (lane & 15);
                int c   = 2 * k16 + (lane >> 4);
                unsigned o = (unsigned)(row * (BK * 2) + ((c ^ (row & AMASK)) * 16));
                LDSM4(ah[mf][0], ah[mf][1], ah[mf][2], ah[mf][3], uA + o);
            }
#pragma unroll
            for (int g = 0; g < 4; g++) {
                int row = k16 * 16 + (lane & 15);
                int c   = nwarp * 8 + g * 2 + (lane >> 4);
                unsigned o = (unsigned)(row * 256 + ((c ^ (row & 7)) * 16));
                unsigned r0, r1, r2, r3;
                unsigned b0[2], b1[2];
                LDSM4T(r0, r1, r2, r3, uBh + o);
                b0[0] = r0; b0[1] = r1; b1[0] = r2; b1[1] = r3;
#pragma unroll
                for (int mf = 0; mf < 2; mf++) {
                    hmma(acc[mf][2 * g],     ah[mf], b0);
                    hmma(acc[mf][2 * g + 1], ah[mf], b1);
                }
                LDSM4T(r0, r1, r2, r3, uBl + o);
                b0[0] = r0; b0[1] = r1; b1[0] = r2; b1[1] = r3;
#pragma unroll
                for (int mf = 0; mf < 2; mf++) {
                    hmma(acc[mf][2 * g],     ah[mf], b0);
                    hmma(acc[mf][2 * g + 1], ah[mf], b1);
                }
            }
        }
    }

    const int qr = lane >> 2;
    const int qc = (lane & 3) * 2;
    if (EPI == 0) {
#pragma unroll
        for (int mf = 0; mf < 2; mf++) {
            int m1 = bm + mwarp * 32 + mf * 16 + qr;
            int m2 = m1 + 8;
            float d1 = (m1 < NN) ? g_deg[m1] : 0.f;
            float d2 = (m2 < NN) ? g_deg[m2] : 0.f;
#pragma unroll
            for (int nf = 0; nf < 8; nf++) {
                int n = nwarp * 64 + nf * 8 + qc;
                float* c4 = acc[mf][nf];
                if (m1 < NN)
                    *(float2*)&g_xw[(size_t)m1 * H + n] =
                        make_float2(c4[0] * d1, c4[1] * d1);
                if (m2 < NN)
                    *(float2*)&g_xw[(size_t)m2 * H + n] =
                        make_float2(c4[2] * d2, c4[3] * d2);
            }
        }
    } else {
        const float* cb = (EPI == 1) ? (const float*)g_b1f : cbias;
        float* Sg = g_S + ((EPI == 1) ? 0 : NB * H);
        auto bt_at = [&](int m) -> int {
            return is64b ? (int)bt64[m] : bt32[m];
        };
        const int gt0 = bt_at(min(bm, NN - 1));
        // per-warp graph-uniformity (batch is sorted)
        const int w0 = bm + mwarp * 32;
        const int gA = bt_at(min(w0, NN - 1));
        const int gB = bt_at(min(w0 + 31, NN - 1));
        const bool uni = (gA == gB);

        float fs[8][2], fq[8][2];
#pragma unroll
        for (int nf = 0; nf < 8; nf++) {
            fs[nf][0] = fs[nf][1] = 0.f;
            fq[nf][0] = fq[nf][1] = 0.f;
        }
#pragma unroll
        for (int mf = 0; mf < 2; mf++) {
            int m1 = bm + mwarp * 32 + mf * 16 + qr;
            int m2 = m1 + 8;
            int g1 = (m1 < NN) ? bt_at(m1) : -1;
            int g2 = (m2 < NN) ? bt_at(m2) : -1;
#pragma unroll
            for (int nf = 0; nf < 8; nf++) {
                int n = nwarp * 64 + nf * 8 + qc;
                float2 bb = *(const float2*)&cb[n];
                float* c4 = acc[mf][nf];
                float v0 = 0.f, v1 = 0.f, v2 = 0.f, v3 = 0.f;
                if (m1 < NN) {
                    v0 = fmaxf(c4[0] + bb.x, 0.f);
                    v1 = fmaxf(c4[1] + bb.y, 0.f);
                }
                if (m2 < NN) {
                    v2 = fmaxf(c4[2] + bb.x, 0.f);
                    v3 = fmaxf(c4[3] + bb.y, 0.f);
                }
                if (!uni) {     // per-row S adds (graph boundary in warp span)
                    if (m1 < NN) {
                        int d = g1 - gt0;
                        if (d >= 0 && d < 8) {
                            atomicAdd(&S_loc[d][n], v0);
                            atomicAdd(&S_loc[d][n + 1], v1);
                        } else {
                            atomicAdd(&Sg[(size_t)g1 * H + n], v0);
                            atomicAdd(&Sg[(size_t)g1 * H + n + 1], v1);
                        }
                    }
                    if (m2 < NN) {
                        int d = g2 - gt0;
                        if (d >= 0 && d < 8) {
                            atomicAdd(&S_loc[d][n], v2);
                            atomicAdd(&S_loc[d][n + 1], v3);
                        } else {
                            atomicAdd(&Sg[(size_t)g2 * H + n], v2);
                            atomicAdd(&Sg[(size_t)g2 * H + n + 1], v3);
                        }
                    }
                }
                fs[nf][0] += v0 + v2; fs[nf][1] += v1 + v3;
                fq[nf][0] += v0 * v0 + v2 * v2;
                fq[nf][1] += v1 * v1 + v3 * v3;
            }
        }
#pragma unroll
        for (int off = 4; off <= 16; off <<= 1)
#pragma unroll
            for (int nf = 0; nf < 8; nf++)
#pragma unroll
                for (int j = 0; j < 2; j++) {
                    fs[nf][j] += __shfl_down_sync(0xffffffffu, fs[nf][j], off);
                    fq[nf][j] += __shfl_down_sync(0xffffffffu, fq[nf][j], off);
                }
        if (lane < 4) {
            const int d = gA - gt0;
#pragma unroll
            for (int nf = 0; nf < 8; nf++) {
                int n = nwarp * 64 + nf * 8 + lane * 2;
                atomicAdd(&s_sum[n],     fs[nf][0]);
                atomicAdd(&s_sum[n + 1], fs[nf][1]);
                atomicAdd(&s_sq[n],      fq[nf][0]);
                atomicAdd(&s_sq[n + 1],  fq[nf][1]);
                if (uni) {      // whole warp same graph: add reduced sums once
                    if (d >= 0 && d < 8) {
                        atomicAdd(&S_loc[d][n],     fs[nf][0]);
                        atomicAdd(&S_loc[d][n + 1], fs[nf][1]);
                    } else {
                        atomicAdd(&Sg[(size_t)gA * H + n],     fs[nf][0]);
                        atomicAdd(&Sg[(size_t)gA * H + n + 1], fs[nf][1]);
                    }
                }
            }
        }
        __syncthreads();
        if (tid < H) {
            const int soff = (EPI == 1) ? 2 : 4;
            atomicAdd(&g_stats[(size_t)soff * H + tid], (double)s_sum[tid]);
            atomicAdd(&g_stats[(size_t)(soff + 1) * H + tid], (double)s_sq[tid]);
        }
#pragma unroll
        for (int i = tid; i < 8 * H; i += 256) {
            int slot = i >> 7, n = i & 127;
            float v = S_loc[slot][n];
            int gg = gt0 + slot;
            if (v != 0.f && gg < NB)
                atomicAdd(&Sg[(size_t)gg * H + n], v);
        }
    }
}

// ---------------- pull-mode GCN aggregate -> h0 (fp16) + BN0 stats -----------
__global__ void __launch_bounds__(256) k_gather(const float* __restrict__ bgcn) {
    __shared__ float s_sum[H], s_sq[H];
    const int tid = threadIdx.x, lane = tid & 31, wid = tid >> 5;
    if (tid < H) { s_sum[tid] = 0.f; s_sq[tid] = 0.f; }
    __syncthreads();

    const float4 b4 = *(const float4*)&bgcn[lane * 4];
    float fs[4] = {0, 0, 0, 0}, fq[4] = {0, 0, 0, 0};
    const int step = gridDim.x * 8;

    for (int node = blockIdx.x * 8 + wid; node < NN; node += step) {
        float4 acc = *(const float4*)&g_xw[(size_t)node * H + lane * 4];
        const int base = g_off[node];
        const int cnt  = g_cnt[node];
        for (int c0 = 0; c0 < cnt; c0 += 32) {
            int n = min(cnt - c0, 32);
            int idx = (lane < n) ? g_ssrc[base + c0 + lane] : 0;
            int sc = __shfl_sync(0xffffffffu, idx, 0);
            float4 v = *(const float4*)&g_xw[(size_t)sc * H + lane * 4];
            for (int i = 0; i < n; i++) {
                float4 cur = v;
                if (i + 1 < n) {
                    int sn = __shfl_sync(0xffffffffu, idx, i + 1);
                    v = *(const float4*)&g_xw[(size_t)sn * H + lane * 4];
                }
                acc.x += cur.x; acc.y += cur.y; acc.z += cur.z; acc.w += cur.w;
            }
        }
        const float dv = g_deg[node];
        float h0x = fmaxf(acc.x * dv + b4.x, 0.f);
        float h0y = fmaxf(acc.y * dv + b4.y, 0.f);
        float h0z = fmaxf(acc.z * dv + b4.z, 0.f);
        float h0w = fmaxf(acc.w * dv + b4.w, 0.f);
        *(uint2*)&g_h0h[(size_t)node * 64 + lane * 2] =
            make_uint2(h2pack(h0x, h0y), h2pack(h0z, h0w));
        fs[0] += h0x; fs[1] += h0y; fs[2] += h0z; fs[3] += h0w;
        fq[0] += h0x * h0x; fq[1] += h0y * h0y;
        fq[2] += h0z * h0z; fq[3] += h0w * h0w;
    }

#pragma unroll
    for (int j = 0; j < 4; j++) {
        atomicAdd(&s_sum[lane * 4 + j], fs[j]);
        atomicAdd(&s_sq[lane * 4 + j], fq[j]);
    }
    __syncthreads();
    if (tid < H) {
        atomicAdd(&g_stats[0 * H + tid], (double)s_sum[tid]);
        atomicAdd(&g_stats[1 * H + tid], (double)s_sq[tid]);
    }
}

// ------------------------- fold BN0 into W1 ----------------------------------
__global__ void k_fold1(const float* __restrict__ g0, const float* __restrict__ be0,
                        const float* __restrict__ W1, const float* __restrict__ b1) {
    __shared__ float s0[H], t0[H];
    const int f = threadIdx.x;
    double mu  = g_stats[0 * H + f] / (double)NN;
    double var = g_stats[1 * H + f] / (double)NN - mu * mu;
    float  r   = (float)(1.0 / sqrt(var + 1e-5));
    float  sf  = g0[f] * r;
    float  tf  = be0[f] - (float)mu * sf;
    s0[f] = sf; t0[f] = tf;
    __syncthreads();
    float bacc = b1[f];
    for (int k = 0; k < H; k++) {
        float w = W1[k * H + f];
        g_W1f[k * H + f] = s0[k] * w;
        bacc += t0[k] * w;
    }
    g_b1f[f] = bacc;
}

// ------------------------- fold BN1/BN2 + W3 ---------------------------------
__global__ void k_fold3(const float* __restrict__ g1, const float* __restrict__ be1,
                        const float* __restrict__ g2, const float* __restrict__ be2,
                        const float* __restrict__ W3, const float* __restrict__ b3) {
    const int f = threadIdx.x;
    double mu1 = g_stats[2 * H + f] / (double)NN;
    double v1  = g_stats[3 * H + f] / (double)NN - mu1 * mu1;
    float  r1  = (float)(1.0 / sqrt(v1 + 1e-5));
    float  s1  = g1[f] * r1;
    float  t1  = be1[f] - (float)mu1 * s1;
    double mu2 = g_stats[4 * H + f] / (double)NN;
    double v2  = g_stats[5 * H + f] / (double)NN - mu2 * mu2;
    float  r2  = (float)(1.0 / sqrt(v2 + 1e-5));
    float  s2  = g2[f] * r2;
    float  t2  = be2[f] - (float)mu2 * s2;
    float w3a = W3[f], w3b = W3[H + f];
    g_W3a[f] = w3a * s1;
    g_W3b[f] = w3b * s2;
    __shared__ double red[H];
    red[f] = (double)(t1 * w3a) + (double)(t2 * w3b);
    __syncthreads();
    for (int o = 64; o > 0; o >>= 1) {
        if (f < o) red[f] += red[f + o];
        __syncthreads();
    }
    if (f == 0) g_c = (float)red[0] + b3[0];
}

// ------------------------- per-graph output ----------------------------------
__global__ void k_out(float* __restrict__ out, const float* __restrict__ b3) {
    const int lane = threadIdx.x & 31;
    const int b    = blockIdx.x * 8 + (threadIdx.x >> 5);
    if (b >= NB) return;
    float z = 0.f;
#pragma unroll
    for (int f = lane; f < H; f += 32)
        z += g_S[(size_t)b * H + f] * g_W3a[f] +
             g_S[(size_t)(NB + b) * H + f] * g_W3b[f];
#pragma unroll
    for (int o = 16; o > 0; o >>= 1) z += __shfl_xor_sync(0xffffffffu, z, o);
    if (lane == 0) {
        float c = g_gcnt[b];
        out[b] = (c > 0.f) ? (z / c + g_c) : b3[0];
    }
}

// ------------------------- launch ---------------------------------------------
extern "C" void kernel_launch(void* const* d_in, const int* in_sizes, int n_in,
                              void* d_out, int out_size) {
    const float* x      = (const float*)d_in[0];
    const float* action = (const float*)d_in[1];
    const float* W_gcn  = (const float*)d_in[2];
    const float* b_gcn  = (const float*)d_in[3];
    const float* g0     = (const float*)d_in[4];
    const float* be0    = (const float*)d_in[5];
    const float* W1     = (const float*)d_in[6];
    const float* b1     = (const float*)d_in[7];
    const float* g1     = (const float*)d_in[8];
    const float* be1    = (const float*)d_in[9];
    const float* W2     = (const float*)d_in[10];
    const float* b2     = (const float*)d_in[11];
    const float* g2     = (const float*)d_in[12];
    const float* be2    = (const float*)d_in[13];
    const float* W3     = (const float*)d_in[14];
    const float* b3     = (const float*)d_in[15];
    const long long* e64 = (const long long*)d_in[16];
    const int*       e32 = (const int*)d_in[16];
    const long long* bt64 = (const long long*)d_in[17];
    const int*       bt32 = (const int*)d_in[17];
    float* out = (float*)d_out;

    const int GBLK = (NN + 127) / 128;   // 1563
    // smem: ASZ + 2*BSZ + 1024 (stats) + 4096 (S_loc)
    const int SM64  = (128 * 64 * 2) + 2 * (64 * 128 * 2) + 1024 + 4096; // 54272
    const int SM128 = SM64;
    const int SM32  = (128 * 32 * 2) + 2 * (32 * 128 * 2) + 1024 + 4096; // 29696

    cudaFuncSetAttribute(k_bmma<64, 0>,
                         cudaFuncAttributeMaxDynamicSharedMemorySize, SM64);
    cudaFuncSetAttribute(k_bmma<128, 1>,
                         cudaFuncAttributeMaxDynamicSharedMemorySize, SM128);
    cudaFuncSetAttribute(k_bmma<32, 2>,
                         cudaFuncAttributeMaxDynamicSharedMemorySize, SM32);

    k_detect<<<1, 32>>>(e64);
    k_init<<<(2 * NB * H + 255) / 256, 256>>>();
    k_bhist<<<(NN + 255) / 256, 256>>>(bt64, bt32);
    k_hist<<<1024, 256>>>(e64, e32);
    k_scan1<<<NBLK, 256>>>();
    k_scan2<<<1, 256>>>();
    k_scan3<<<NBLK, 256>>>();
    k_sortedges<<<1024, 256>>>(e64, e32);
    k_prep<0><<<32, 256>>>(W_gcn);
    k_prep<2><<<16, 256>>>(W2);
    k_bmma<64, 0><<<GBLK, 256, SM64>>>(x, nullptr, bt64, bt32);
    k_gather<<<1536, 256>>>(b_gcn);
    k_fold1<<<1, H>>>(g0, be0, W1, b1);
    k_prep<1><<<64, 256>>>(nullptr);
    k_bmma<128, 1><<<GBLK, 256, SM128>>>(nullptr, nullptr, bt64, bt32);
    k_bmma<32, 2><<<GBLK, 256, SM32>>>(action, b2, bt64, bt32);
    k_fold3<<<1, H>>>(g1, be1, g2, be2, W3, b3);
    k_out<<<(NB + 7) / 8, 256>>>(out, b3);
}

// round 14
// speedup vs baseline: 1.3978x; 1.3978x over previous
#include <cuda_runtime.h>
#include <cuda_fp16.h>
#include <math.h>

#define NN 200000
#define NE 1600000
#define NB 1000
#define H  128
#define NBLK 196          // ceil(NN/1024)

// ------------------------- device scratch (no allocs allowed) ----------------
__device__ unsigned g_xwh[(size_t)NN * 64]; // dinv*xW_gcn as packed half2
__device__ unsigned g_h0h[(size_t)NN * 64]; // h0 as packed half2
__device__ float    g_h1 [(size_t)NN * H];  // h1 (fp32)
__device__ float    g_xw [(size_t)NN * H];  // h2 (fp32)
__device__ float    g_deg[NN];              // dinv
__device__ double   g_stats[6 * H];         // sum0,sq0,sum1,sq1,sum2,sq2
__device__ float    g_W1f[H * H];           // BN0-folded W1
__device__ float    g_b1f[H];
__device__ float    g_W3a[H], g_W3b[H];
__device__ float    g_c;
__device__ float    g_gsum[NB], g_gcnt[NB];
__device__ int      g_is64;
// CSR-ish edge structures (counting sort by dst)
__device__ int      g_cnt[NN];
__device__ int      g_off[NN];
__device__ int      g_cur[NN];
__device__ int      g_ssrc[NE];
__device__ int      g_bsum[256];
// Pre-split, pre-swizzled fp16 hi/lo weight images (SMEM-verbatim layout)
__device__ __align__(16) unsigned char g_Bh[65536];
__device__ __align__(16) unsigned char g_Bl[65536];

// ------------------------- small helpers -------------------------------------
__device__ __forceinline__ unsigned smem_u32(const void* p) {
    unsigned a;
    asm("{ .reg .u64 t; cvta.to.shared.u64 t, %1; cvt.u32.u64 %0, t; }"
        : "=r"(a) : "l"(p));
    return a;
}
__device__ __forceinline__ unsigned h2pack(float a, float b) {
    __half2 h = __floats2half2_rn(a, b);
    return *(unsigned*)&h;
}
__device__ __forceinline__ float2 h2unpack(unsigned u) {
    return __half22float2(*(__half2*)&u);
}

#define LDSM4(r0, r1, r2, r3, a) \
    asm volatile("ldmatrix.sync.aligned.m8n8.x4.shared.b16 {%0,%1,%2,%3}, [%4];" \
                 : "=r"(r0), "=r"(r1), "=r"(r2), "=r"(r3) : "r"(a))
#define LDSM4T(r0, r1, r2, r3, a) \
    asm volatile("ldmatrix.sync.aligned.m8n8.x4.trans.shared.b16 {%0,%1,%2,%3}, [%4];" \
                 : "=r"(r0), "=r"(r1), "=r"(r2), "=r"(r3) : "r"(a))

__device__ __forceinline__ void hmma(float* c, const unsigned* a, const unsigned* b) {
    asm volatile(
        "mma.sync.aligned.m16n8k16.row.col.f32.f16.f16.f32 "
        "{%0,%1,%2,%3}, {%4,%5,%6,%7}, {%8,%9}, {%0,%1,%2,%3};"
        : "+f"(c[0]), "+f"(c[1]), "+f"(c[2]), "+f"(c[3])
        : "r"(a[0]), "r"(a[1]), "r"(a[2]), "r"(a[3]), "r"(b[0]), "r"(b[1]));
}

// ------------------------- misc small kernels --------------------------------
__global__ void k_detect(const long long* __restrict__ ei) {
    if (threadIdx.x == 0) {
        int ok = 1;
        for (int i = 0; i < 128; i++) {
            long long v = ei[i];
            if (v < 0 || v >= NN) ok = 0;
        }
        g_is64 = ok;
    }
}
__global__ void k_init() {
    int i = blockIdx.x * blockDim.x + threadIdx.x;
    if (i < NN) g_cnt[i] = 0;
    if (i < 6 * H) g_stats[i] = 0.0;
    if (i < NB) { g_gsum[i] = 0.f; g_gcnt[i] = 0.f; }
}
__global__ void k_hist(const long long* __restrict__ e64,
                       const int* __restrict__ e32) {
    int is64 = g_is64;
    for (int e = blockIdx.x * blockDim.x + threadIdx.x; e < NE;
         e += gridDim.x * blockDim.x) {
        int d = is64 ? (int)e64[NE + e] : e32[NE + e];
        atomicAdd(&g_cnt[d], 1);
    }
}
__global__ void k_scan1() {
    __shared__ int sh[256];
    int blk = blockIdx.x, tid = threadIdx.x;
    int s = 0;
#pragma unroll
    for (int k = 0; k < 4; k++) {
        int i = blk * 1024 + tid + k * 256;
        if (i < NN) s += g_cnt[i];
    }
    sh[tid] = s; __syncthreads();
    for (int o = 128; o > 0; o >>= 1) {
        if (tid < o) sh[tid] += sh[tid + o];
        __syncthreads();
    }
    if (tid == 0) g_bsum[blk] = sh[0];
}
__global__ void k_scan2() {
    __shared__ int sh[256];
    int t = threadIdx.x;
    int v = (t < NBLK) ? g_bsum[t] : 0;
    sh[t] = v; __syncthreads();
    for (int o = 1; o < 256; o <<= 1) {
        int a = (t >= o) ? sh[t - o] : 0;
        __syncthreads();
        sh[t] += a;
        __syncthreads();
    }
    if (t < NBLK) g_bsum[t] = sh[t] - v;
}
__global__ void k_scan3() {
    __shared__ int tsum[256];
    int blk = blockIdx.x, tid = threadIdx.x;
    int i0 = blk * 1024 + tid * 4;
    int v[4];
#pragma unroll
    for (int j = 0; j < 4; j++) v[j] = (i0 + j < NN) ? g_cnt[i0 + j] : 0;
    int s = v[0] + v[1] + v[2] + v[3];
    tsum[tid] = s; __syncthreads();
    for (int o = 1; o < 256; o <<= 1) {
        int a = (tid >= o) ? tsum[tid - o] : 0;
        __syncthreads();
        tsum[tid] += a;
        __syncthreads();
    }
    int off = g_bsum[blk] + tsum[tid] - s;
#pragma unroll
    for (int j = 0; j < 4; j++) {
        int i = i0 + j;
        if (i < NN) {
            g_off[i] = off;
            g_cur[i] = off;
            g_deg[i] = rsqrtf((float)v[j] + 1.0f);
            off += v[j];
        }
    }
}
__global__ void k_sortedges(const long long* __restrict__ e64,
                            const int* __restrict__ e32) {
    int is64 = g_is64;
    for (int e = blockIdx.x * blockDim.x + threadIdx.x; e < NE;
         e += gridDim.x * blockDim.x) {
        int s, d;
        if (is64) { s = (int)e64[e]; d = (int)e64[NE + e]; }
        else      { s = e32[e];      d = e32[NE + e]; }
        int pos = atomicAdd(&g_cur[d], 1);
        g_ssrc[pos] = s;
    }
}

// ------------------------- weight prep: fp16 split + pre-swizzle -------------
template<int WHICH>
__global__ void k_prep(const float* __restrict__ srcp) {
    const int K   = (WHICH == 0) ? 64 : (WHICH == 1) ? 128 : 32;
    const int off = (WHICH == 0) ? 0 : (WHICH == 1) ? 16384 : 49152;
    const float* src = (WHICH == 1) ? (const float*)g_W1f : srcp;
    int idx = blockIdx.x * blockDim.x + threadIdx.x;
    if (idx >= K * 128) return;
    int k = idx >> 7, n = idx & 127;
    float v = src[k * 128 + n];
    __half h = __float2half_rn(v);
    __half l = __float2half_rn(v - __half2float(h));
    unsigned o = (unsigned)(k * 256 + (((n >> 3) ^ (k & 7)) * 16) + (n & 7) * 2);
    *(unsigned short*)(g_Bh + off + o) = __half_as_ushort(h);
    *(unsigned short*)(g_Bl + off + o) = __half_as_ushort(l);
}

// ------- fp16 mma.sync GEMM (2-pass: A*Bh + A*Bl): C[128,128]=A[128,K]@W ----
// EPI 0: g_xwh = fp16(C * dinv).                          (A=x fp32, K=64)
// EPI 1: A = g_h0h (fp16 copy); g_h1 = relu(C + g_b1f); stats[2],[3]. (K=128)
// EPI 2: g_xw = relu(C + cbias); stats[4],[5].            (A=action, K=32)
template<int K, int EPI>
__global__ void __launch_bounds__(256, 2)
k_bmma(const float* __restrict__ Aext, const float* __restrict__ cbias) {
    constexpr int BK    = (K < 64) ? K : 64;
    constexpr int NST   = K / BK;
    constexpr int CPR   = BK / 8;
    constexpr int AMASK = (CPR < 8 ? CPR : 8) - 1;
    constexpr int ASZ   = 128 * BK * 2;
    constexpr int BSZ   = BK * 128 * 2;
    extern __shared__ __align__(128) unsigned char smem[];
    unsigned char* A_im = smem;
    unsigned char* B_hi = smem + ASZ;
    unsigned char* B_lo = smem + ASZ + BSZ;
    float* s_sum = (float*)(smem + ASZ + 2 * BSZ);
    float* s_sq  = s_sum + H;

    const int tid   = threadIdx.x;
    const int lane  = tid & 31;
    const int wid   = tid >> 5;
    const int mwarp = wid & 3;
    const int nwarp = wid >> 2;
    const int bm    = blockIdx.x * 128;
    const float* A  = Aext;
    const int boff  = (EPI == 0) ? 0 : (EPI == 1) ? 16384 : 49152;

    if (EPI != 0 && tid < H) { s_sum[tid] = 0.f; s_sq[tid] = 0.f; }

    const unsigned uA  = smem_u32(A_im);
    const unsigned uBh = smem_u32(B_hi);
    const unsigned uBl = smem_u32(B_lo);

    float acc[2][8][4];
#pragma unroll
    for (int i = 0; i < 2; i++)
#pragma unroll
        for (int j = 0; j < 8; j++)
#pragma unroll
            for (int q = 0; q < 4; q++) acc[i][j][q] = 0.f;

    for (int st = 0; st < NST; st++) {
        if (st > 0) __syncthreads();

        {   // copy pre-swizzled B stage (L2-hot)
            const uint4* sh = (const uint4*)(g_Bh + boff + st * BK * 256);
            const uint4* sl = (const uint4*)(g_Bl + boff + st * BK * 256);
            uint4* dh = (uint4*)B_hi;
            uint4* dl = (uint4*)B_lo;
#pragma unroll
            for (int i = tid; i < BSZ / 16; i += 256) {
                dh[i] = sh[i]; dl[i] = sl[i];
            }
        }
        {   // build A fp16 image for this k-stage
            const int row0 = tid / CPR;
            const int c    = tid % CPR;
#pragma unroll
            for (int pass = 0; pass < CPR / 2; pass++) {
                int m  = row0 + pass * (256 / CPR);
                int gr = bm + m;
                uint4 hp;
                if (EPI == 1) {
                    hp = (gr < NN)
                        ? *(const uint4*)&g_h0h[(size_t)gr * 64 + (st * 8 + c) * 4]
                        : make_uint4(0, 0, 0, 0);
                } else {
                    const int kc = st * BK + c * 8;
                    float v[8];
                    if (gr < NN) {
                        float4 x0 = *(const float4*)&A[(size_t)gr * K + kc];
                        float4 x1 = *(const float4*)&A[(size_t)gr * K + kc + 4];
                        v[0] = x0.x; v[1] = x0.y; v[2] = x0.z; v[3] = x0.w;
                        v[4] = x1.x; v[5] = x1.y; v[6] = x1.z; v[7] = x1.w;
                    } else {
#pragma unroll
                        for (int j = 0; j < 8; j++) v[j] = 0.f;
                    }
                    hp.x = h2pack(v[0], v[1]);
                    hp.y = h2pack(v[2], v[3]);
                    hp.z = h2pack(v[4], v[5]);
                    hp.w = h2pack(v[6], v[7]);
                }
                unsigned o = (unsigned)(m * (BK * 2) + ((c ^ (m & AMASK)) * 16));
                *(uint4*)(A_im + o) = hp;
            }
        }
        __syncthreads();

#pragma unroll
        for (int k16 = 0; k16 < BK / 16; k16++) {
            unsigned ah[2][4];
#pragma unroll
            for (int mf = 0; mf < 2; mf++) {
                int row = mwarp * 32 + mf * 16 + (lane & 15);
                int c   = 2 * k16 + (lane >> 4);
                unsigned o = (unsigned)(row * (BK * 2) + ((c ^ (row & AMASK)) * 16));
                LDSM4(ah[mf][0], ah[mf][1], ah[mf][2], ah[mf][3], uA + o);
            }
#pragma unroll
            for (int g = 0; g < 4; g++) {
                int row = k16 * 16 + (lane & 15);
                int c   = nwarp * 8 + g * 2 + (lane >> 4);
                unsigned o = (unsigned)(row * 256 + ((c ^ (row & 7)) * 16));
                unsigned r0, r1, r2, r3;
                unsigned b0[2], b1[2];
                LDSM4T(r0, r1, r2, r3, uBh + o);
                b0[0] = r0; b0[1] = r1; b1[0] = r2; b1[1] = r3;
#pragma unroll
                for (int mf = 0; mf < 2; mf++) {
                    hmma(acc[mf][2 * g],     ah[mf], b0);
                    hmma(acc[mf][2 * g + 1], ah[mf], b1);
                }
                LDSM4T(r0, r1, r2, r3, uBl + o);
                b0[0] = r0; b0[1] = r1; b1[0] = r2; b1[1] = r3;
#pragma unroll
                for (int mf = 0; mf < 2; mf++) {
                    hmma(acc[mf][2 * g],     ah[mf], b0);
                    hmma(acc[mf][2 * g + 1], ah[mf], b1);
                }
            }
        }
    }

    const int qr = lane >> 2;
    const int qc = (lane & 3) * 2;
    if (EPI == 0) {
#pragma unroll
        for (int mf = 0; mf < 2; mf++) {
            int m1 = bm + mwarp * 32 + mf * 16 + qr;
            int m2 = m1 + 8;
            float d1 = (m1 < NN) ? g_deg[m1] : 0.f;
            float d2 = (m2 < NN) ? g_deg[m2] : 0.f;
#pragma unroll
            for (int nf = 0; nf < 8; nf++) {
                int n = nwarp * 64 + nf * 8 + qc;
                float* c4 = acc[mf][nf];
                if (m1 < NN)
                    g_xwh[(size_t)m1 * 64 + (n >> 1)] =
                        h2pack(c4[0] * d1, c4[1] * d1);
                if (m2 < NN)
                    g_xwh[(size_t)m2 * 64 + (n >> 1)] =
                        h2pack(c4[2] * d2, c4[3] * d2);
            }
        }
    } else {
        float* dst = (EPI == 1) ? (float*)g_h1 : (float*)g_xw;
        const float* cb = (EPI == 1) ? (const float*)g_b1f : cbias;
        float fs[8][2], fq[8][2];
#pragma unroll
        for (int nf = 0; nf < 8; nf++) {
            fs[nf][0] = fs[nf][1] = 0.f;
            fq[nf][0] = fq[nf][1] = 0.f;
        }
#pragma unroll
        for (int mf = 0; mf < 2; mf++) {
            int m1 = bm + mwarp * 32 + mf * 16 + qr;
            int m2 = m1 + 8;
#pragma unroll
            for (int nf = 0; nf < 8; nf++) {
                int n = nwarp * 64 + nf * 8 + qc;
                float2 bb = *(const float2*)&cb[n];
                float* c4 = acc[mf][nf];
                float v0 = fmaxf(c4[0] + bb.x, 0.f);
                float v1 = fmaxf(c4[1] + bb.y, 0.f);
                float v2 = fmaxf(c4[2] + bb.x, 0.f);
                float v3 = fmaxf(c4[3] + bb.y, 0.f);
                if (m1 < NN)
                    *(float2*)&dst[(size_t)m1 * H + n] = make_float2(v0, v1);
                else { v0 = 0.f; v1 = 0.f; }
                if (m2 < NN)
                    *(float2*)&dst[(size_t)m2 * H + n] = make_float2(v2, v3);
                else { v2 = 0.f; v3 = 0.f; }
                fs[nf][0] += v0 + v2; fs[nf][1] += v1 + v3;
                fq[nf][0] += v0 * v0 + v2 * v2;
                fq[nf][1] += v1 * v1 + v3 * v3;
            }
        }
#pragma unroll
        for (int off = 4; off <= 16; off <<= 1)
#pragma unroll
            for (int nf = 0; nf < 8; nf++)
#pragma unroll
                for (int j = 0; j < 2; j++) {
                    fs[nf][j] += __shfl_down_sync(0xffffffffu, fs[nf][j], off);
                    fq[nf][j] += __shfl_down_sync(0xffffffffu, fq[nf][j], off);
                }
        if (lane < 4) {
#pragma unroll
            for (int nf = 0; nf < 8; nf++) {
                int n = nwarp * 64 + nf * 8 + lane * 2;
                atomicAdd(&s_sum[n],     fs[nf][0]);
                atomicAdd(&s_sum[n + 1], fs[nf][1]);
                atomicAdd(&s_sq[n],      fq[nf][0]);
                atomicAdd(&s_sq[n + 1],  fq[nf][1]);
            }
        }
        __syncthreads();
        if (tid < H) {
            const int soff = (EPI == 1) ? 2 : 4;
            atomicAdd(&g_stats[(size_t)soff * H + tid], (double)s_sum[tid]);
            atomicAdd(&g_stats[(size_t)(soff + 1) * H + tid], (double)s_sq[tid]);
        }
    }
}

// ---------------- pull-mode GCN aggregate (fp16 msgs) -> fp16 h0 + BN0 stats -
__global__ void __launch_bounds__(256) k_gather(const float* __restrict__ bgcn) {
    __shared__ float s_sum[H], s_sq[H];
    const int tid = threadIdx.x, lane = tid & 31, wid = tid >> 5;
    if (tid < H) { s_sum[tid] = 0.f; s_sq[tid] = 0.f; }
    __syncthreads();

    const float4 b4 = *(const float4*)&bgcn[lane * 4];
    float fs[4] = {0, 0, 0, 0}, fq[4] = {0, 0, 0, 0};
    const int step = gridDim.x * 8;

    for (int node = blockIdx.x * 8 + wid; node < NN; node += step) {
        uint2 p0 = *(const uint2*)&g_xwh[(size_t)node * 64 + lane * 2];
        float2 a0 = h2unpack(p0.x), a1 = h2unpack(p0.y);
        float4 acc = make_float4(a0.x, a0.y, a1.x, a1.y);
        const int base = g_off[node];
        const int cnt  = g_cnt[node];
        for (int c0 = 0; c0 < cnt; c0 += 32) {
            int n = min(cnt - c0, 32);
            int idx = (lane < n) ? g_ssrc[base + c0 + lane] : 0;
            int sc = __shfl_sync(0xffffffffu, idx, 0);
            uint2 v = *(const uint2*)&g_xwh[(size_t)sc * 64 + lane * 2];
            for (int i = 0; i < n; i++) {
                uint2 cur = v;
                if (i + 1 < n) {
                    int sn = __shfl_sync(0xffffffffu, idx, i + 1);
                    v = *(const uint2*)&g_xwh[(size_t)sn * 64 + lane * 2];
                }
                float2 c0f = h2unpack(cur.x), c1f = h2unpack(cur.y);
                acc.x += c0f.x; acc.y += c0f.y; acc.z += c1f.x; acc.w += c1f.y;
            }
        }
        const float dv = g_deg[node];
        float h0x = fmaxf(acc.x * dv + b4.x, 0.f);
        float h0y = fmaxf(acc.y * dv + b4.y, 0.f);
        float h0z = fmaxf(acc.z * dv + b4.z, 0.f);
        float h0w = fmaxf(acc.w * dv + b4.w, 0.f);
        *(uint2*)&g_h0h[(size_t)node * 64 + lane * 2] =
            make_uint2(h2pack(h0x, h0y), h2pack(h0z, h0w));
        fs[0] += h0x; fs[1] += h0y; fs[2] += h0z; fs[3] += h0w;
        fq[0] += h0x * h0x; fq[1] += h0y * h0y;
        fq[2] += h0z * h0z; fq[3] += h0w * h0w;
    }

#pragma unroll
    for (int j = 0; j < 4; j++) {
        atomicAdd(&s_sum[lane * 4 + j], fs[j]);
        atomicAdd(&s_sq[lane * 4 + j], fq[j]);
    }
    __syncthreads();
    if (tid < H) {
        atomicAdd(&g_stats[0 * H + tid], (double)s_sum[tid]);
        atomicAdd(&g_stats[1 * H + tid], (double)s_sq[tid]);
    }
}

// ------------------------- fold BN0 into W1 ----------------------------------
__global__ void k_fold1(const float* __restrict__ g0, const float* __restrict__ be0,
                        const float* __restrict__ W1, const float* __restrict__ b1) {
    __shared__ float s0[H], t0[H];
    const int f = threadIdx.x;
    double mu  = g_stats[0 * H + f] / (double)NN;
    double var = g_stats[1 * H + f] / (double)NN - mu * mu;
    float  r   = (float)(1.0 / sqrt(var + 1e-5));
    float  sf  = g0[f] * r;
    float  tf  = be0[f] - (float)mu * sf;
    s0[f] = sf; t0[f] = tf;
    __syncthreads();
    float bacc = b1[f];
    for (int k = 0; k < H; k++) {
        float w = W1[k * H + f];
        g_W1f[k * H + f] = s0[k] * w;
        bacc += t0[k] * w;
    }
    g_b1f[f] = bacc;
}

// ------------------------- fold BN1/BN2 + W3 ---------------------------------
__global__ void k_fold3(const float* __restrict__ g1, const float* __restrict__ be1,
                        const float* __restrict__ g2, const float* __restrict__ be2,
                        const float* __restrict__ W3, const float* __restrict__ b3) {
    const int f = threadIdx.x;
    double mu1 = g_stats[2 * H + f] / (double)NN;
    double v1  = g_stats[3 * H + f] / (double)NN - mu1 * mu1;
    float  r1  = (float)(1.0 / sqrt(v1 + 1e-5));
    float  s1  = g1[f] * r1;
    float  t1  = be1[f] - (float)mu1 * s1;
    double mu2 = g_stats[4 * H + f] / (double)NN;
    double v2  = g_stats[5 * H + f] / (double)NN - mu2 * mu2;
    float  r2  = (float)(1.0 / sqrt(v2 + 1e-5));
    float  s2  = g2[f] * r2;
    float  t2  = be2[f] - (float)mu2 * s2;
    float w3a = W3[f], w3b = W3[H + f];
    g_W3a[f] = w3a * s1;
    g_W3b[f] = w3b * s2;
    __shared__ double red[H];
    red[f] = (double)(t1 * w3a) + (double)(t2 * w3b);
    __syncthreads();
    for (int o = 64; o > 0; o >>= 1) {
        if (f < o) red[f] += red[f + o];
        __syncthreads();
    }
    if (f == 0) g_c = (float)red[0] + b3[0];
}

// ------------------------- per-node scalar + segment sum ---------------------
__global__ void k_z(const long long* __restrict__ b64, const int* __restrict__ b32) {
    const int is64 = g_is64;
    const int lane = threadIdx.x & 31;
    const int n    = (blockIdx.x * blockDim.x + threadIdx.x) >> 5;
    if (n >= NN) return;
    float4 a  = *(const float4*)&g_h1[(size_t)n * H + lane * 4];
    float4 b  = *(const float4*)&g_xw[(size_t)n * H + lane * 4];   // h2
    float4 wa = *(const float4*)&g_W3a[lane * 4];
    float4 wb = *(const float4*)&g_W3b[lane * 4];
    float z = a.x * wa.x + a.y * wa.y + a.z * wa.z + a.w * wa.w +
              b.x * wb.x + b.y * wb.y + b.z * wb.z + b.w * wb.w;
#pragma unroll
    for (int o = 16; o > 0; o >>= 1) z += __shfl_xor_sync(0xffffffffu, z, o);
    if (lane == 0) {
        int g = is64 ? (int)b64[n] : b32[n];
        atomicAdd(&g_gsum[g], z);
        atomicAdd(&g_gcnt[g], 1.0f);
    }
}

__global__ void k_final(float* __restrict__ out, const float* __restrict__ b3) {
    int b = blockIdx.x * blockDim.x + threadIdx.x;
    if (b < NB) {
        float c = g_gcnt[b];
        out[b] = (c > 0.f) ? (g_gsum[b] / c + g_c) : b3[0];
    }
}

// ------------------------- launch ---------------------------------------------
extern "C" void kernel_launch(void* const* d_in, const int* in_sizes, int n_in,
                              void* d_out, int out_size) {
    const float* x      = (const float*)d_in[0];
    const float* action = (const float*)d_in[1];
    const float* W_gcn  = (const float*)d_in[2];
    const float* b_gcn  = (const float*)d_in[3];
    const float* g0     = (const float*)d_in[4];
    const float* be0    = (const float*)d_in[5];
    const float* W1     = (const float*)d_in[6];
    const float* b1     = (const float*)d_in[7];
    const float* g1     = (const float*)d_in[8];
    const float* be1    = (const float*)d_in[9];
    const float* W2     = (const float*)d_in[10];
    const float* b2     = (const float*)d_in[11];
    const float* g2     = (const float*)d_in[12];
    const float* be2    = (const float*)d_in[13];
    const float* W3     = (const float*)d_in[14];
    const float* b3     = (const float*)d_in[15];
    const long long* e64 = (const long long*)d_in[16];
    const int*       e32 = (const int*)d_in[16];
    const long long* bt64 = (const long long*)d_in[17];
    const int*       bt32 = (const int*)d_in[17];
    float* out = (float*)d_out;

    const int GBLK = (NN + 127) / 128;   // 1563
    // smem: ASZ + 2*BSZ + 1024, BK=min(K,64)
    const int SM64  = (128 * 64 * 2) + 2 * (64 * 128 * 2) + 1024;  // 50176
    const int SM128 = SM64;
    const int SM32  = (128 * 32 * 2) + 2 * (32 * 128 * 2) + 1024;  // 25600

    cudaFuncSetAttribute(k_bmma<64, 0>,
                         cudaFuncAttributeMaxDynamicSharedMemorySize, SM64);
    cudaFuncSetAttribute(k_bmma<128, 1>,
                         cudaFuncAttributeMaxDynamicSharedMemorySize, SM128);
    cudaFuncSetAttribute(k_bmma<32, 2>,
                         cudaFuncAttributeMaxDynamicSharedMemorySize, SM32);

    k_detect<<<1, 32>>>(e64);
    k_init<<<(NN + 255) / 256, 256>>>();
    k_hist<<<1024, 256>>>(e64, e32);
    k_scan1<<<NBLK, 256>>>();
    k_scan2<<<1, 256>>>();
    k_scan3<<<NBLK, 256>>>();
    k_sortedges<<<1024, 256>>>(e64, e32);
    k_prep<0><<<32, 256>>>(W_gcn);
    k_prep<2><<<16, 256>>>(W2);
    k_bmma<64, 0><<<GBLK, 256, SM64>>>(x, nullptr);         // xw' -> fp16
    k_gather<<<1536, 256>>>(b_gcn);                         // h0 (fp16) + stats
    k_fold1<<<1, H>>>(g0, be0, W1, b1);
    k_prep<1><<<64, 256>>>(nullptr);                        // W1f -> fp16
    k_bmma<128, 1><<<GBLK, 256, SM128>>>(nullptr, nullptr); // h1
    k_bmma<32, 2><<<GBLK, 256, SM32>>>(action, b2);         // h2 -> g_xw
    k_fold3<<<1, H>>>(g1, be1, g2, be2, W3, b3);
    k_z<<<NN / 8, 256>>>(bt64, bt32);
    k_final<<<4, 256>>>(out, b3);
}